// round 17
// baseline (speedup 1.0000x reference)
#include <cuda_runtime.h>
#include <math.h>

#define B 4
#define L 1024
#define D 512
#define H 8
#define DK 64
#define DF 2048
#define NL 2
#define HWIN 6
#define SCALE 0.125f
#define NEG -1e9f
#define EPS 1e-5f
#define ROWS (B*L)
#define BH (B*H)

// ---- scratch (device globals; no allocations allowed) ----
__device__ float g_q[B*L*D];
__device__ float g_k[B*L*D];
__device__ float g_v[B*L*D];
__device__ float g_x[B*L*D];
__device__ float g_tmp[B*L*D];
__device__ float g_ao[B*L*D];
__device__ float g_ff[B*L*DF];
__device__ float g_zero[D];                  // zero bias for split z=1
__device__ float g_scores[(size_t)BH*L*L];   // masked pre-softmax scores (carried across layers)

// ============================================================
// helpers: raw-bit tf32 (HW truncates), mma, cp.async
// ============================================================
__device__ __forceinline__ void mma8(float* d, const unsigned* a, const unsigned* b) {
    asm volatile("mma.sync.aligned.m16n8k8.row.col.f32.tf32.tf32.f32 "
                 "{%0,%1,%2,%3}, {%4,%5,%6,%7}, {%8,%9}, {%0,%1,%2,%3};\n"
                 : "+f"(d[0]), "+f"(d[1]), "+f"(d[2]), "+f"(d[3])
                 : "r"(a[0]), "r"(a[1]), "r"(a[2]), "r"(a[3]),
                   "r"(b[0]), "r"(b[1]));
}
__device__ __forceinline__ void cpa16(float* s, const float* g) {
    unsigned a = (unsigned)__cvta_generic_to_shared(s);
    asm volatile("cp.async.cg.shared.global [%0], [%1], 16;\n" :: "r"(a), "l"(g));
}
#define CP_COMMIT() asm volatile("cp.async.commit_group;\n" ::: "memory")
#define CP_WAIT0()  asm volatile("cp.async.wait_group 0;\n" ::: "memory")
#define CP_WAIT1()  asm volatile("cp.async.wait_group 1;\n" ::: "memory")

// dynamic smem layout for GEMM: 3 stages (R7/R11 config)
#define AST 2560
#define BST 2176
#define GEMM_SMEM (3*(AST+BST)*4)   // 56832 bytes

// ============================================================
// GEMM body (R13/R14 winner): 128x128 tile, BK=16, 3-stage cp.async,
// single barrier per K-tile.
// ============================================================
template<int GELU>
__device__ __forceinline__ void gemm_body(const float* __restrict__ A,
                                          const float* __restrict__ W,
                                          const float* __restrict__ bias,
                                          float* __restrict__ C,
                                          int N, int K, int bm, int bn,
                                          float* smA, float* smB) {
    int tid = threadIdx.x;
    int lane = tid & 31, w = tid >> 5;
    int grp = lane >> 2, tg = lane & 3;
    int wm = (w >> 1) * 32, wn = (w & 1) * 64;
    int ar = tid >> 1, ac = (tid & 1) * 8;
    int br = tid >> 4, bc = (tid & 15) * 8;

    float acc[2][8][4];
    #pragma unroll
    for (int i = 0; i < 2; i++)
        #pragma unroll
        for (int j = 0; j < 8; j++)
            #pragma unroll
            for (int c = 0; c < 4; c++) acc[i][j][c] = 0.f;

    const float* Ap = A + (size_t)(bm + ar) * K + ac;
    const float* Wp = W + (size_t)br * N + bn + bc;
    int T = K >> 4;

    auto issue = [&](int t) {
        int s = t % 3;
        const float* a = Ap + (t << 4);
        cpa16(&smA[s*AST + ar*20 + ac],     a);
        cpa16(&smA[s*AST + ar*20 + ac + 4], a + 4);
        const float* bsrc = Wp + (size_t)(t << 4) * N;
        cpa16(&smB[s*BST + br*136 + bc],     bsrc);
        cpa16(&smB[s*BST + br*136 + bc + 4], bsrc + 4);
    };

    if (0 < T) issue(0);
    CP_COMMIT();
    if (1 < T) issue(1);
    CP_COMMIT();

    for (int t = 0; t < T; t++) {
        CP_WAIT1();
        __syncthreads();
        if (t + 2 < T) issue(t + 2);
        CP_COMMIT();
        const float* As = &smA[(t % 3) * AST];
        const float* Bs = &smB[(t % 3) * BST];
        #pragma unroll
        for (int ks = 0; ks < 16; ks += 8) {
            unsigned af[2][4], bf[8][2];
            #pragma unroll
            for (int mi = 0; mi < 2; mi++) {
                int m = wm + mi * 16 + grp;
                af[mi][0] = __float_as_uint(As[m*20 + ks + tg]);
                af[mi][1] = __float_as_uint(As[(m+8)*20 + ks + tg]);
                af[mi][2] = __float_as_uint(As[m*20 + ks + tg + 4]);
                af[mi][3] = __float_as_uint(As[(m+8)*20 + ks + tg + 4]);
            }
            #pragma unroll
            for (int ni = 0; ni < 8; ni++) {
                int n = wn + ni * 8 + grp;
                bf[ni][0] = __float_as_uint(Bs[(ks+tg)*136 + n]);
                bf[ni][1] = __float_as_uint(Bs[(ks+tg+4)*136 + n]);
            }
            #pragma unroll
            for (int mi = 0; mi < 2; mi++)
                #pragma unroll
                for (int ni = 0; ni < 8; ni++)
                    mma8(acc[mi][ni], af[mi], bf[ni]);
        }
    }

    #pragma unroll
    for (int mi = 0; mi < 2; mi++)
        #pragma unroll
        for (int ni = 0; ni < 8; ni++) {
            int row = bm + wm + mi * 16 + grp;
            int col = bn + wn + ni * 8 + tg * 2;
            float bs0 = bias[col], bs1 = bias[col + 1];
            float v0 = acc[mi][ni][0] + bs0, v1 = acc[mi][ni][1] + bs1;
            float v2 = acc[mi][ni][2] + bs0, v3 = acc[mi][ni][3] + bs1;
            if (GELU) {
                v0 = 0.5f * v0 * (1.0f + erff(v0 * 0.70710678118654752f));
                v1 = 0.5f * v1 * (1.0f + erff(v1 * 0.70710678118654752f));
                v2 = 0.5f * v2 * (1.0f + erff(v2 * 0.70710678118654752f));
                v3 = 0.5f * v3 * (1.0f + erff(v3 * 0.70710678118654752f));
            }
            float2* p0 = (float2*)(C + (size_t)row * N + col);
            float2* p1 = (float2*)(C + (size_t)(row + 8) * N + col);
            *p0 = make_float2(v0, v1);
            *p1 = make_float2(v2, v3);
        }
}

template<int GELU>
__device__ __forceinline__ void gemm_body_stride(const float* __restrict__ A,
                                                 const float* __restrict__ W,
                                                 const float* __restrict__ bias,
                                                 float* __restrict__ C,
                                                 int N, int K, int Kst, int bm, int bn,
                                                 float* smA, float* smB) {
    int tid = threadIdx.x;
    int lane = tid & 31, w = tid >> 5;
    int grp = lane >> 2, tg = lane & 3;
    int wm = (w >> 1) * 32, wn = (w & 1) * 64;
    int ar = tid >> 1, ac = (tid & 1) * 8;
    int br = tid >> 4, bc = (tid & 15) * 8;

    float acc[2][8][4];
    #pragma unroll
    for (int i = 0; i < 2; i++)
        #pragma unroll
        for (int j = 0; j < 8; j++)
            #pragma unroll
            for (int c = 0; c < 4; c++) acc[i][j][c] = 0.f;

    const float* Ap = A + (size_t)(bm + ar) * Kst + ac;
    const float* Wp = W + (size_t)br * N + bn + bc;
    int T = K >> 4;

    auto issue = [&](int t) {
        int s = t % 3;
        const float* a = Ap + (t << 4);
        cpa16(&smA[s*AST + ar*20 + ac],     a);
        cpa16(&smA[s*AST + ar*20 + ac + 4], a + 4);
        const float* bsrc = Wp + (size_t)(t << 4) * N;
        cpa16(&smB[s*BST + br*136 + bc],     bsrc);
        cpa16(&smB[s*BST + br*136 + bc + 4], bsrc + 4);
    };

    if (0 < T) issue(0);
    CP_COMMIT();
    if (1 < T) issue(1);
    CP_COMMIT();

    for (int t = 0; t < T; t++) {
        CP_WAIT1();
        __syncthreads();
        if (t + 2 < T) issue(t + 2);
        CP_COMMIT();
        const float* As = &smA[(t % 3) * AST];
        const float* Bs = &smB[(t % 3) * BST];
        #pragma unroll
        for (int ks = 0; ks < 16; ks += 8) {
            unsigned af[2][4], bf[8][2];
            #pragma unroll
            for (int mi = 0; mi < 2; mi++) {
                int m = wm + mi * 16 + grp;
                af[mi][0] = __float_as_uint(As[m*20 + ks + tg]);
                af[mi][1] = __float_as_uint(As[(m+8)*20 + ks + tg]);
                af[mi][2] = __float_as_uint(As[m*20 + ks + tg + 4]);
                af[mi][3] = __float_as_uint(As[(m+8)*20 + ks + tg + 4]);
            }
            #pragma unroll
            for (int ni = 0; ni < 8; ni++) {
                int n = wn + ni * 8 + grp;
                bf[ni][0] = __float_as_uint(Bs[(ks+tg)*136 + n]);
                bf[ni][1] = __float_as_uint(Bs[(ks+tg+4)*136 + n]);
            }
            #pragma unroll
            for (int mi = 0; mi < 2; mi++)
                #pragma unroll
                for (int ni = 0; ni < 8; ni++)
                    mma8(acc[mi][ni], af[mi], bf[ni]);
        }
    }

    #pragma unroll
    for (int mi = 0; mi < 2; mi++)
        #pragma unroll
        for (int ni = 0; ni < 8; ni++) {
            int row = bm + wm + mi * 16 + grp;
            int col = bn + wn + ni * 8 + tg * 2;
            float bs0 = bias[col], bs1 = bias[col + 1];
            float v0 = acc[mi][ni][0] + bs0, v1 = acc[mi][ni][1] + bs1;
            float v2 = acc[mi][ni][2] + bs0, v3 = acc[mi][ni][3] + bs1;
            float2* p0 = (float2*)(C + (size_t)row * N + col);
            float2* p1 = (float2*)(C + (size_t)(row + 8) * N + col);
            *p0 = make_float2(v0, v1);
            *p1 = make_float2(v2, v3);
        }
}

template<int GELU>
__global__ __launch_bounds__(256, 2) void gemm_tf32(const float* __restrict__ A,
                                                    const float* __restrict__ W,
                                                    const float* __restrict__ bias,
                                                    float* __restrict__ C,
                                                    int N, int K) {
    extern __shared__ float dyn[];
    gemm_body<GELU>(A, W, bias, C, N, K, blockIdx.y * 128, blockIdx.x * 128,
                    dyn, dyn + 3*AST);
}

// split-K GEMM: gridDim.z=2; z picks k-half. z=0 adds bias -> C0; z=1 zero-bias -> C1.
__global__ __launch_bounds__(256, 2) void gemm_split(const float* __restrict__ A,
                                                     const float* __restrict__ W,
                                                     const float* __restrict__ bias,
                                                     const float* __restrict__ zbias,
                                                     float* __restrict__ C0,
                                                     float* __restrict__ C1,
                                                     int N, int Khalf, int Kst) {
    extern __shared__ float dyn[];
    int z = blockIdx.z;
    gemm_body_stride<0>(A + (size_t)z * Khalf,
                        W + (size_t)z * Khalf * N,
                        z ? zbias : bias,
                        z ? C1 : C0,
                        N, Khalf, Kst, blockIdx.y * 128, blockIdx.x * 128,
                        dyn, dyn + 3*AST);
}

// fused QKV: blockIdx.x in [0,12): sel = bx>>2 picks {q,k,v}, (bx&3) n-tile.
__global__ __launch_bounds__(256, 2) void qkv_gemm(const float* __restrict__ A,
        const float* __restrict__ Wq, const float* __restrict__ bq,
        const float* __restrict__ Wk, const float* __restrict__ bk,
        const float* __restrict__ Wv, const float* __restrict__ bv,
        float* __restrict__ q, float* __restrict__ k, float* __restrict__ v) {
    extern __shared__ float dyn[];
    int sel = blockIdx.x >> 2;
    const float* W = sel == 0 ? Wq : (sel == 1 ? Wk : Wv);
    const float* bias = sel == 0 ? bq : (sel == 1 ? bk : bv);
    float* C = sel == 0 ? q : (sel == 1 ? k : v);
    gemm_body<0>(A, W, bias, C, D, D, blockIdx.y * 128, (blockIdx.x & 3) * 128,
                 dyn, dyn + 3*AST);
}

// ============================================================
// Single-pass fused attention, cp.async K+V staging (j-major smem):
// per j-tile: {K,V} arrive as one cp.async group (double-buffered, issued
// 2 tiles ahead); QK over 8 k8-slabs; epilogue -> scores + Ps; PV; 3 barriers.
// Q lives in registers (af[8][2][4]); staged once through Ps area.
// smem (floats): Ks[2][128][72]=18432 | Vs[2][128][72]=18432 | Ps[128][132]=16896
// ============================================================
#define ATT_KS 0
#define ATT_VS 18432
#define ATT_PS 36864
#define ATT_BSTRIDE 9216
#define ATT_SMEM (53760*4)   // 215040 bytes

__global__ __launch_bounds__(256) void attn_fused(const float* __restrict__ q,
                                                  const float* __restrict__ k,
                                                  const float* __restrict__ v,
                                                  float* __restrict__ scores,
                                                  float* __restrict__ ao,
                                                  int add_prev) {
    __shared__ float m_part[2][128];
    __shared__ float inv_row[128];
    extern __shared__ float u[];
    float* Ps = u + ATT_PS;

    int bh = blockIdx.y;
    int b = bh >> 3, h = bh & 7;
    int i0 = blockIdx.x * 128;
    int tid = threadIdx.x, lane = tid & 31, w = tid >> 5;
    int grp = lane >> 2, tg = lane & 3;
    int wm = (w >> 1) * 32, wn = (w & 1) * 64, wn2 = (w & 1) * 32;

    const float* kbase = k + (size_t)b * L * D + h * DK;
    const float* vbase = v + (size_t)b * L * D + h * DK;
    float* sb = scores + (size_t)bh * L * L;
    int vr = tid >> 1, vc = (tid & 1) * 32;

    auto issueKV = [&](int jt) {
        const float* ks = kbase + (size_t)(jt * 128 + vr) * D + vc;
        const float* vs = vbase + (size_t)(jt * 128 + vr) * D + vc;
        float* kd = u + ATT_KS + (jt & 1) * ATT_BSTRIDE + vr * 72 + vc;
        float* vd = u + ATT_VS + (jt & 1) * ATT_BSTRIDE + vr * 72 + vc;
        #pragma unroll
        for (int i = 0; i < 8; i++) cpa16(kd + i * 4, ks + i * 4);
        #pragma unroll
        for (int i = 0; i < 8; i++) cpa16(vd + i * 4, vs + i * 4);
        CP_COMMIT();
    };

    issueKV(0);
    issueKV(1);

    // stage Q strip [128][64] -> Ps area (row stride 68), read frags to regs
    {
        const float4* qsrc = (const float4*)(q + ((size_t)b * L + i0) * D + h * DK);
        #pragma unroll
        for (int it = 0; it < 8; it++) {
            int idx = tid + it * 256;
            int row = idx >> 4, c4 = idx & 15;
            float4 t = qsrc[(size_t)row * (D / 4) + c4];
            float* dst = &Ps[row * 68 + c4 * 4];
            dst[0] = t.x; dst[1] = t.y; dst[2] = t.z; dst[3] = t.w;
        }
    }
    __syncthreads();
    unsigned af[8][2][4];
    #pragma unroll
    for (int ks = 0; ks < 8; ks++)
        #pragma unroll
        for (int mi = 0; mi < 2; mi++) {
            int m = wm + mi * 16 + grp;
            af[ks][mi][0] = __float_as_uint(Ps[m * 68 + ks * 8 + tg]);
            af[ks][mi][1] = __float_as_uint(Ps[(m + 8) * 68 + ks * 8 + tg]);
            af[ks][mi][2] = __float_as_uint(Ps[m * 68 + ks * 8 + tg + 4]);
            af[ks][mi][3] = __float_as_uint(Ps[(m + 8) * 68 + ks * 8 + tg + 4]);
        }
    __syncthreads();

    float acc[2][8][4];
    float acc2[2][4][4];
    float sum_acc[4] = {0.f, 0.f, 0.f, 0.f};
    #pragma unroll
    for (int i = 0; i < 2; i++) {
        #pragma unroll
        for (int j = 0; j < 8; j++)
            #pragma unroll
            for (int c = 0; c < 4; c++) acc[i][j][c] = 0.f;
        #pragma unroll
        for (int j = 0; j < 4; j++)
            #pragma unroll
            for (int c = 0; c < 4; c++) acc2[i][j][c] = 0.f;
    }

    for (int jt = 0; jt < 8; jt++) {
        if (jt == 7) { CP_WAIT0(); } else { CP_WAIT1(); }
        __syncthreads();                 // Ks/Vs(jt) visible to all
        const float* Kb = u + ATT_KS + (jt & 1) * ATT_BSTRIDE;

        // ---- QK^T: 8 k8-slabs ----
        #pragma unroll
        for (int ks = 0; ks < 8; ks++) {
            unsigned bf[8][2];
            #pragma unroll
            for (int ni = 0; ni < 8; ni++) {
                int n = wn + ni * 8 + grp;
                bf[ni][0] = __float_as_uint(Kb[n * 72 + ks*8 + tg]);
                bf[ni][1] = __float_as_uint(Kb[n * 72 + ks*8 + tg + 4]);
            }
            #pragma unroll
            for (int mi = 0; mi < 2; mi++)
                #pragma unroll
                for (int ni = 0; ni < 8; ni++)
                    mma8(acc[mi][ni], af[ks][mi], bf[ni]);
        }

        // ---- epilogue: scores(global) + p -> Ps ----
        #pragma unroll
        for (int mi = 0; mi < 2; mi++)
            #pragma unroll
            for (int ni = 0; ni < 8; ni++) {
                int rl = wm + mi * 16 + grp;
                int cl = wn + ni * 8 + tg * 2;
                int gj = jt * 128 + cl;
                #pragma unroll
                for (int rr = 0; rr < 2; rr++) {
                    int row = i0 + rl + rr * 8;
                    float s0 = acc[mi][ni][rr*2 + 0] * SCALE;
                    float s1 = acc[mi][ni][rr*2 + 1] * SCALE;
                    float2* p = (float2*)(sb + (size_t)row * L + gj);
                    if (add_prev) { float2 pv = *p; s0 += pv.x; s1 += pv.y; }
                    int d0 = row - gj;     d0 = d0 < 0 ? -d0 : d0;
                    int d1 = row - gj - 1; d1 = d1 < 0 ? -d1 : d1;
                    if (d0 < HWIN) s0 = NEG;
                    if (d1 < HWIN) s1 = NEG;
                    *p = make_float2(s0, s1);
                    float p0 = __expf(s0), p1 = __expf(s1);
                    sum_acc[mi*2 + rr] += p0 + p1;
                    float2* pp = (float2*)&Ps[(rl + rr*8) * 132 + cl];
                    *pp = make_float2(p0, p1);
                    acc[mi][ni][rr*2 + 0] = 0.f;
                    acc[mi][ni][rr*2 + 1] = 0.f;
                }
            }
        __syncthreads();                 // Ps published (cross-warp reads next)

        // ---- PV: acc2 += P(128x128) @ V(128x64) ----
        const float* Vb = u + ATT_VS + (jt & 1) * ATT_BSTRIDE;
        #pragma unroll
        for (int ksl = 0; ksl < 16; ksl++) {
            unsigned a2[2][4], b2[4][2];
            #pragma unroll
            for (int mi = 0; mi < 2; mi++) {
                int m = wm + mi * 16 + grp;
                a2[mi][0] = __float_as_uint(Ps[m * 132 + ksl*8 + tg]);
                a2[mi][1] = __float_as_uint(Ps[(m + 8) * 132 + ksl*8 + tg]);
                a2[mi][2] = __float_as_uint(Ps[m * 132 + ksl*8 + tg + 4]);
                a2[mi][3] = __float_as_uint(Ps[(m + 8) * 132 + ksl*8 + tg + 4]);
            }
            #pragma unroll
            for (int ni = 0; ni < 4; ni++) {
                int n = wn2 + ni * 8 + grp;
                b2[ni][0] = __float_as_uint(Vb[(ksl*8 + tg) * 72 + n]);
                b2[ni][1] = __float_as_uint(Vb[(ksl*8 + tg + 4) * 72 + n]);
            }
            #pragma unroll
            for (int mi = 0; mi < 2; mi++)
                #pragma unroll
                for (int ni = 0; ni < 4; ni++)
                    mma8(acc2[mi][ni], a2[mi], b2[ni]);
        }
        __syncthreads();                 // all reads of Ks/Vs(jt), Ps done
        if (jt + 2 < 8) issueKV(jt + 2); // overwrites buffer (jt&1) safely
    }

    // ---- row-sum reduction ----
    #pragma unroll
    for (int mi = 0; mi < 2; mi++)
        #pragma unroll
        for (int rr = 0; rr < 2; rr++) {
            float s = sum_acc[mi*2 + rr];
            s += __shfl_xor_sync(0xffffffffu, s, 1);
            s += __shfl_xor_sync(0xffffffffu, s, 2);
            if (tg == 0) m_part[w & 1][wm + mi*16 + grp + rr*8] = s;
        }
    __syncthreads();
    if (tid < 128) inv_row[tid] = 1.0f / (m_part[0][tid] + m_part[1][tid]);
    __syncthreads();

    float* ob = ao + (size_t)b * L * D + h * DK;
    #pragma unroll
    for (int mi = 0; mi < 2; mi++)
        #pragma unroll
        for (int ni = 0; ni < 4; ni++) {
            int rl = wm + mi * 16 + grp;
            int col = wn2 + ni * 8 + tg * 2;
            float iv0 = inv_row[rl], iv1 = inv_row[rl + 8];
            float2* p0 = (float2*)(ob + (size_t)(i0 + rl) * D + col);
            float2* p1 = (float2*)(ob + (size_t)(i0 + rl + 8) * D + col);
            *p0 = make_float2(acc2[mi][ni][0] * iv0, acc2[mi][ni][1] * iv0);
            *p1 = make_float2(acc2[mi][ni][2] * iv1, acc2[mi][ni][3] * iv1);
        }
}

// ============================================================
// out = LayerNorm(x + r1 + r2) * gamma + beta. 128 thr per row of 512.
// ============================================================
__global__ void addln3_kernel(const float* __restrict__ x, const float* __restrict__ r1,
                              const float* __restrict__ r2,
                              const float* __restrict__ gam, const float* __restrict__ bet,
                              float* __restrict__ out) {
    int row = blockIdx.x;
    int tid = threadIdx.x;
    const float4* xp = (const float4*)(x + (size_t)row * D);
    const float4* r1p = (const float4*)(r1 + (size_t)row * D);
    const float4* r2p = (const float4*)(r2 + (size_t)row * D);
    float4 a = xp[tid], b4 = r1p[tid], c4 = r2p[tid];
    float e0 = a.x + b4.x + c4.x, e1 = a.y + b4.y + c4.y;
    float e2 = a.z + b4.z + c4.z, e3 = a.w + b4.w + c4.w;
    float s = e0 + e1 + e2 + e3;
    float qq = e0*e0 + e1*e1 + e2*e2 + e3*e3;
    __shared__ float rs[4], rq[4];
    #pragma unroll
    for (int off = 16; off; off >>= 1) {
        s  += __shfl_xor_sync(0xffffffffu, s, off);
        qq += __shfl_xor_sync(0xffffffffu, qq, off);
    }
    if ((tid & 31) == 0) { rs[tid >> 5] = s; rq[tid >> 5] = qq; }
    __syncthreads();
    s  = rs[0] + rs[1] + rs[2] + rs[3];
    qq = rq[0] + rq[1] + rq[2] + rq[3];
    float mean = s * (1.0f / D);
    float var  = qq * (1.0f / D) - mean * mean;
    float inv  = rsqrtf(var + EPS);
    float4 g4 = ((const float4*)gam)[tid];
    float4 bb = ((const float4*)bet)[tid];
    float4 ov;
    ov.x = (e0 - mean) * inv * g4.x + bb.x;
    ov.y = (e1 - mean) * inv * g4.y + bb.y;
    ov.z = (e2 - mean) * inv * g4.z + bb.z;
    ov.w = (e3 - mean) * inv * g4.w + bb.w;
    ((float4*)(out + (size_t)row * D))[tid] = ov;
}

// ============================================================
extern "C" void kernel_launch(void* const* d_in, const int* in_sizes, int n_in,
                              void* d_out, int out_size) {
    const float* src = (const float*)d_in[0];
    const float* Wq = (const float*)d_in[1];  const float* bq = (const float*)d_in[2];
    const float* Wk = (const float*)d_in[3];  const float* bk = (const float*)d_in[4];
    const float* Wv = (const float*)d_in[5];  const float* bv = (const float*)d_in[6];
    const float* Wo = (const float*)d_in[7];  const float* bo = (const float*)d_in[8];
    const float* W1 = (const float*)d_in[9];  const float* b1 = (const float*)d_in[10];
    const float* W2 = (const float*)d_in[11]; const float* b2 = (const float*)d_in[12];
    const float* ln1g = (const float*)d_in[13]; const float* ln1b = (const float*)d_in[14];
    const float* ln2g = (const float*)d_in[15]; const float* ln2b = (const float*)d_in[16];

    float *q, *k, *v, *x, *tmp, *ao, *ff, *sc, *zb;
    cudaGetSymbolAddress((void**)&q,  g_q);
    cudaGetSymbolAddress((void**)&k,  g_k);
    cudaGetSymbolAddress((void**)&v,  g_v);
    cudaGetSymbolAddress((void**)&x,  g_x);
    cudaGetSymbolAddress((void**)&tmp, g_tmp);
    cudaGetSymbolAddress((void**)&ao, g_ao);
    cudaGetSymbolAddress((void**)&ff, g_ff);
    cudaGetSymbolAddress((void**)&sc, g_scores);
    cudaGetSymbolAddress((void**)&zb, g_zero);

    cudaFuncSetAttribute(gemm_tf32<0>, cudaFuncAttributeMaxDynamicSharedMemorySize, GEMM_SMEM);
    cudaFuncSetAttribute(gemm_tf32<1>, cudaFuncAttributeMaxDynamicSharedMemorySize, GEMM_SMEM);
    cudaFuncSetAttribute(gemm_split,   cudaFuncAttributeMaxDynamicSharedMemorySize, GEMM_SMEM);
    cudaFuncSetAttribute(qkv_gemm,     cudaFuncAttributeMaxDynamicSharedMemorySize, GEMM_SMEM);
    cudaFuncSetAttribute(attn_fused,   cudaFuncAttributeMaxDynamicSharedMemorySize, ATT_SMEM);

    dim3 gDF(DF/128, ROWS/128);      // 16 x 32 (FF1)
    dim3 gQKV(12, ROWS/128);         // 12 x 32
    dim3 gA(L/128, BH);              // 8 x 32
    dim3 gSplit(D/128, ROWS/128, 2); // 4 x 32 x 2 (Wo, FF2)

    const float* xin = src;
    for (int l = 0; l < NL; l++) {
        qkv_gemm<<<gQKV, 256, GEMM_SMEM>>>(xin,
            Wq + (size_t)l*D*D, bq + (size_t)l*D,
            Wk + (size_t)l*D*D, bk + (size_t)l*D,
            Wv + (size_t)l*D*D, bv + (size_t)l*D, q, k, v);
        attn_fused<<<gA, 256, ATT_SMEM>>>(q, k, v, sc, ao, l > 0 ? 1 : 0);
        gemm_split<<<gSplit, 256, GEMM_SMEM>>>(ao, Wo + (size_t)l*D*D,
            bo + (size_t)l*D, zb, tmp, q, D, D/2, D);
        addln3_kernel<<<ROWS, 128>>>(xin, tmp, q,
            ln1g + (size_t)l*D, ln1b + (size_t)l*D, x);
        gemm_tf32<1><<<gDF, 256, GEMM_SMEM>>>(x, W1 + (size_t)l*D*DF, b1 + (size_t)l*DF, ff, DF, D);
        gemm_split<<<gSplit, 256, GEMM_SMEM>>>(ff, W2 + (size_t)l*DF*D,
            b2 + (size_t)l*D, zb, tmp, q, D, DF/2, DF);
        float* lnout = (l == NL-1) ? (float*)d_out : x;
        addln3_kernel<<<ROWS, 128>>>(x, tmp, q,
            ln2g + (size_t)l*D, ln2b + (size_t)l*D, lnout);
        xin = x;
    }
}